// round 1
// baseline (speedup 1.0000x reference)
#include <cuda_runtime.h>
#include <cuda_bf16.h>
#include <math_constants.h>

// Problem constants (fixed-shape problem)
#define D 128
#define N_MAX 500000

// Scratch for per-row logits (2 MB, L2-resident). __device__ global: allowed.
__device__ float g_src[N_MAX];

__global__ __launch_bounds__(256) void seg_attn_kernel(
    const float* __restrict__ x,
    const float* __restrict__ refm,
    const int*   __restrict__ index,
    const float* __restrict__ W,
    const float* __restrict__ bptr,
    float*       __restrict__ out,
    int n)
{
    const int s    = blockIdx.x;
    const int tid  = threadIdx.x;
    const int w    = tid >> 5;
    const int lane = tid & 31;

    __shared__ int   seg_bounds[2];
    __shared__ float warp_val[8];
    __shared__ float red_max, red_inv;
    __shared__ float acc_s[8][D];   // 4 KB

    // Segment bounds via binary search in sorted index (thread 0)
    if (tid == 0) {
        int lo = 0, hi = n;
        while (lo < hi) { int mid = (lo + hi) >> 1; if (index[mid] < s) lo = mid + 1; else hi = mid; }
        seg_bounds[0] = lo;
        hi = n;
        while (lo < hi) { int mid = (lo + hi) >> 1; if (index[mid] < s + 1) lo = mid + 1; else hi = mid; }
        seg_bounds[1] = lo;
    }
    __syncthreads();
    const int start = seg_bounds[0];
    const int end   = seg_bounds[1];

    if (end == start) {                 // empty segment -> zeros (d_out is poisoned)
        if (tid < D) out[(size_t)s * D + tid] = 0.0f;
        return;
    }

    // W in registers: lane owns columns [4*lane, 4*lane+3] of each half
    const float4 Wa = ((const float4*)W)[lane];        // W[0:128]
    const float4 Wb = ((const float4*)W)[32 + lane];   // W[128:256]
    const float  bb = bptr[0];

    // ---- Phase A: logits + per-warp max (warp w handles rows start+w, +8, ...) ----
    float wmax = -CUDART_INF_F;
    for (int r = start + w; r < end; r += 8) {
        const float4 xv = ((const float4*)(x    + (size_t)r * D))[lane];
        const float4 rv = ((const float4*)(refm + (size_t)r * D))[lane];
        float p = xv.x * Wa.x + xv.y * Wa.y + xv.z * Wa.z + xv.w * Wa.w
                + rv.x * Wb.x + rv.y * Wb.y + rv.z * Wb.z + rv.w * Wb.w;
        #pragma unroll
        for (int o = 16; o; o >>= 1) p += __shfl_down_sync(0xffffffffu, p, o);
        if (lane == 0) {
            float srcv = tanhf(p + bb);
            g_src[r] = srcv;
            wmax = fmaxf(wmax, srcv);
        }
    }
    if (lane == 0) warp_val[w] = wmax;
    __syncthreads();
    if (tid == 0) {
        float m = warp_val[0];
        #pragma unroll
        for (int i = 1; i < 8; i++) m = fmaxf(m, warp_val[i]);
        red_max = m;
    }
    __syncthreads();
    const float mx = red_max;

    // ---- Phase B1: sum of exp(src - max), all 256 threads ----
    float psum = 0.0f;
    for (int r = start + tid; r < end; r += 256) {
        psum += __expf(g_src[r] - mx);
    }
    #pragma unroll
    for (int o = 16; o; o >>= 1) psum += __shfl_down_sync(0xffffffffu, psum, o);
    if (lane == 0) warp_val[w] = psum;
    __syncthreads();
    if (tid == 0) {
        float ssum = 0.0f;
        #pragma unroll
        for (int i = 0; i < 8; i++) ssum += warp_val[i];
        red_inv = 1.0f / (ssum + 1e-16f);
    }
    __syncthreads();
    const float invs = red_inv;

    // ---- Phase B2: out[s,:] = sum_r w_r * x[r,:]  (x re-read from L2) ----
    float4 a = make_float4(0.f, 0.f, 0.f, 0.f);
    for (int r = start + w; r < end; r += 8) {
        const float wi = __expf(g_src[r] - mx) * invs;   // broadcast scalar load
        const float4 xv = ((const float4*)(x + (size_t)r * D))[lane];
        a.x += wi * xv.x; a.y += wi * xv.y; a.z += wi * xv.z; a.w += wi * xv.w;
    }
    ((float4*)acc_s[w])[lane] = a;
    __syncthreads();
    if (tid < D) {
        float sum = 0.0f;
        #pragma unroll
        for (int i = 0; i < 8; i++) sum += acc_s[i][tid];
        out[(size_t)s * D + tid] = sum;
    }
}

extern "C" void kernel_launch(void* const* d_in, const int* in_sizes, int n_in,
                              void* d_out, int out_size) {
    // metadata order: x, ref, index, batch_size, W, b
    const float* x     = (const float*)d_in[0];
    const float* refm  = (const float*)d_in[1];
    const int*   index = (const int*)  d_in[2];
    const float* W     = (const float*)d_in[4];
    const float* b     = (const float*)d_in[5];
    float* out = (float*)d_out;

    const int n = in_sizes[0] / D;        // 500000
    const int B = out_size / D;           // 16384

    seg_attn_kernel<<<B, 256>>>(x, refm, index, W, b, out, n);
}

// round 2
// speedup vs baseline: 1.5992x; 1.5992x over previous
#include <cuda_runtime.h>
#include <cuda_bf16.h>

#define D 128
#define B_MAX 16384

__device__ int g_starts[B_MAX + 1];

__global__ void bounds_kernel(const int* __restrict__ index, int n, int B) {
    int s = blockIdx.x * blockDim.x + threadIdx.x;
    if (s > B) return;
    if (s == B) { g_starts[B] = n; return; }
    int lo = 0, hi = n;
    while (lo < hi) { int mid = (lo + hi) >> 1; if (index[mid] < s) lo = mid + 1; else hi = mid; }
    g_starts[s] = lo;
}

__device__ __forceinline__ float fast_tanh(float v) {
    float r;
    asm("tanh.approx.f32 %0, %1;" : "=f"(r) : "f"(v));
    return r;
}

__global__ __launch_bounds__(256) void seg_attn_kernel(
    const float* __restrict__ x,
    const float* __restrict__ refm,
    const float* __restrict__ W,
    const float* __restrict__ bptr,
    float*       __restrict__ out)
{
    const int s    = blockIdx.x;
    const int tid  = threadIdx.x;
    const int w    = tid >> 5;
    const int lane = tid & 31;

    __shared__ float acc_s[8][D];   // 4 KB
    __shared__ float esum_s[8];

    const int start = g_starts[s];
    const int end   = g_starts[s + 1];

    if (start == end) {                       // empty segment -> zeros
        if (tid < D) out[(size_t)s * D + tid] = 0.0f;
        return;
    }

    // W in registers: lane owns feature columns [4*lane, 4*lane+3]
    const float4 Wa = ((const float4*)W)[lane];        // x half
    const float4 Wb = ((const float4*)W)[32 + lane];   // ref half
    const float  bb = bptr[0];

    float4 acc  = make_float4(0.f, 0.f, 0.f, 0.f);
    float  esum = 0.f;

    // Single pass, 4 rows per warp per iteration (8 LDG.128 in flight)
    for (int r0 = start + w * 4; r0 < end; r0 += 32) {
        float4 xv[4];
        float  p[4];
        #pragma unroll
        for (int k = 0; k < 4; k++) {
            const int r = r0 + k;
            float4 rv = make_float4(0.f, 0.f, 0.f, 0.f);
            xv[k] = rv;
            if (r < end) {   // predicated loads
                xv[k] = ((const float4*)(x    + (size_t)r * D))[lane];
                rv    = ((const float4*)(refm + (size_t)r * D))[lane];
            }
            p[k] = xv[k].x * Wa.x + xv[k].y * Wa.y + xv[k].z * Wa.z + xv[k].w * Wa.w
                 + rv.x    * Wb.x + rv.y    * Wb.y + rv.z    * Wb.z + rv.w    * Wb.w;
        }
        // 4 interleaved butterfly trees: every lane ends with full row-sums
        #pragma unroll
        for (int o = 16; o; o >>= 1) {
            #pragma unroll
            for (int k = 0; k < 4; k++)
                p[k] += __shfl_xor_sync(0xffffffffu, p[k], o);
        }
        #pragma unroll
        for (int k = 0; k < 4; k++) {
            if (r0 + k < end) {
                const float e = __expf(fast_tanh(p[k] + bb));   // shift-invariant softmax: no seg max needed
                esum  += e;
                acc.x += e * xv[k].x;
                acc.y += e * xv[k].y;
                acc.z += e * xv[k].z;
                acc.w += e * xv[k].w;
            }
        }
    }

    ((float4*)acc_s[w])[lane] = acc;
    if (lane == 0) esum_s[w] = esum;
    __syncthreads();

    if (tid < D) {
        float t = 0.f, es = 0.f;
        #pragma unroll
        for (int i = 0; i < 8; i++) { t += acc_s[i][tid]; es += esum_s[i]; }
        out[(size_t)s * D + tid] = t / (es + 1e-16f);
    }
}

extern "C" void kernel_launch(void* const* d_in, const int* in_sizes, int n_in,
                              void* d_out, int out_size) {
    // metadata order: x, ref, index, batch_size, W, b
    const float* x     = (const float*)d_in[0];
    const float* refm  = (const float*)d_in[1];
    const int*   index = (const int*)  d_in[2];
    const float* W     = (const float*)d_in[4];
    const float* b     = (const float*)d_in[5];
    float* out = (float*)d_out;

    const int n = in_sizes[0] / D;   // 500000
    const int B = out_size / D;      // 16384

    bounds_kernel<<<(B + 256) / 256, 256>>>(index, n, B);
    seg_attn_kernel<<<B, 256>>>(x, refm, W, b, out);
}